// round 13
// baseline (speedup 1.0000x reference)
#include <cuda_runtime.h>
#include <cuda_fp16.h>
#include <cstdint>

namespace {

constexpr int Bn = 2, Ln = 2048, Hn = 16, En = 64;
constexpr int BM = 128, BN = 128;
constexpr int RS = Hn * En;  // 1024 floats between seq positions in Q/O

constexpr uint32_t KSTRIDE = 144;            // 64 fp16 = 128B + 16B pad
constexpr uint32_t TILE = 128 * KSTRIDE;     // 18432 B (128 rows)
constexpr uint32_t BUFB = 2 * TILE;          // Kh, Vh
constexpr uint32_t SMEM_TOTAL = 2 * BUFB;    // 73728 B -> 2 CTAs/SM

constexpr float QSCALE = 0.125f * 1.44269504f;  // (1/sqrt(64)) * log2(e), folded into Q
constexpr uint32_t HONES = 0x3C003C00u;         // fp16x2 {1.0, 1.0}

// Preprocessed fp16 operands, [B, H, L, E] layout (rows of 128B).
constexpr size_t NE = (size_t)Bn * Hn * Ln * En;
__device__ __half Qhg[NE];
__device__ __half Khg[NE];
__device__ __half Vhg[NE];

__device__ __forceinline__ uint32_t packh(float lo, float hi) {
  uint32_t r;
  asm("cvt.rn.f16x2.f32 %0, %1, %2;" : "=r"(r) : "f"(hi), "f"(lo));
  return r;
}
__device__ __forceinline__ float ex2f(float x) {
  float r;
  asm("ex2.approx.f32 %0, %1;" : "=f"(r) : "f"(x));
  return r;
}

__device__ __forceinline__ void mma16816(float (&c)[4], const uint32_t (&a)[4],
                                         uint32_t b0, uint32_t b1) {
  asm volatile(
      "mma.sync.aligned.m16n8k16.row.col.f32.f16.f16.f32 "
      "{%0,%1,%2,%3}, {%4,%5,%6,%7}, {%8,%9}, {%0,%1,%2,%3};"
      : "+f"(c[0]), "+f"(c[1]), "+f"(c[2]), "+f"(c[3])
      : "r"(a[0]), "r"(a[1]), "r"(a[2]), "r"(a[3]), "r"(b0), "r"(b1));
}
__device__ __forceinline__ void ldsm_x4(uint32_t& r0, uint32_t& r1, uint32_t& r2, uint32_t& r3,
                                        uint32_t addr) {
  asm volatile("ldmatrix.sync.aligned.m8n8.x4.shared.b16 {%0,%1,%2,%3}, [%4];"
               : "=r"(r0), "=r"(r1), "=r"(r2), "=r"(r3) : "r"(addr));
}
__device__ __forceinline__ void ldsm_x4_t(uint32_t& r0, uint32_t& r1, uint32_t& r2, uint32_t& r3,
                                          uint32_t addr) {
  asm volatile("ldmatrix.sync.aligned.m8n8.x4.trans.shared.b16 {%0,%1,%2,%3}, [%4];"
               : "=r"(r0), "=r"(r1), "=r"(r2), "=r"(r3) : "r"(addr));
}
__device__ __forceinline__ uint32_t smem_u32(const void* p) {
  uint32_t a;
  asm("{ .reg .u64 t; cvta.to.shared.u64 t, %1; cvt.u32.u64 %0, t; }" : "=r"(a) : "l"(p));
  return a;
}

// ---------------- prep: fp32 [B,L,H,E] -> fp16 [B,H,L,E] ----------------
__global__ void __launch_bounds__(256)
prep(const float* __restrict__ Q, const float* __restrict__ K, const float* __restrict__ V) {
  uint32_t g = blockIdx.x * 256u + threadIdx.x;
  uint32_t e4 = g & 15u, h = (g >> 4) & 15u, l = (g >> 8) & 2047u, b = g >> 19;
  size_t si = (((size_t)b * Ln + l) * Hn + h) * En + 4 * e4;
  size_t di = (((size_t)b * Hn + h) * Ln + l) * En + 4 * e4;

  float4 q = *reinterpret_cast<const float4*>(Q + si);
  float4 k = *reinterpret_cast<const float4*>(K + si);
  float4 v = *reinterpret_cast<const float4*>(V + si);

  q.x *= QSCALE; q.y *= QSCALE; q.z *= QSCALE; q.w *= QSCALE;
  *reinterpret_cast<__half2*>(&Qhg[di]) =
      __halves2half2(__float2half_rn(q.x), __float2half_rn(q.y));
  *reinterpret_cast<__half2*>(&Qhg[di + 2]) =
      __halves2half2(__float2half_rn(q.z), __float2half_rn(q.w));

  *reinterpret_cast<__half2*>(&Khg[di]) =
      __halves2half2(__float2half_rn(k.x), __float2half_rn(k.y));
  *reinterpret_cast<__half2*>(&Khg[di + 2]) =
      __halves2half2(__float2half_rn(k.z), __float2half_rn(k.w));

  *reinterpret_cast<__half2*>(&Vhg[di]) =
      __halves2half2(__float2half_rn(v.x), __float2half_rn(v.y));
  *reinterpret_cast<__half2*>(&Vhg[di + 2]) =
      __halves2half2(__float2half_rn(v.z), __float2half_rn(v.w));
}

// ---------------- attention ----------------
__device__ __forceinline__ void stage_cp(uint32_t sdst, const char* kh, const char* vh, int tid) {
#pragma unroll
  for (int i = 0; i < 8; i++) {
    const int t = i >> 2;  // 0=Kh 1=Vh
    int r = (tid >> 3) + 32 * (i & 3);
    int c = tid & 7;
    const char* src = (t == 0 ? kh : vh) + r * 128 + c * 16;
    uint32_t dst = sdst + (uint32_t)t * TILE + (uint32_t)r * KSTRIDE + 16u * c;
    asm volatile("cp.async.cg.shared.global [%0], [%1], 16;" :: "r"(dst), "l"(src));
  }
}

__global__ void __launch_bounds__(256, 2)
attn_mma(float* __restrict__ O) {
  extern __shared__ __align__(16) char smem[];
  const uint32_t sb = smem_u32(smem);

  const int tid = threadIdx.x;
  const int w = tid >> 5, lane = tid & 31;
  const int g = lane >> 2, tq = lane & 3;

  const int qt = (int)gridDim.x - 1 - (int)blockIdx.x;  // heavy tiles first
  const int h = blockIdx.y, b = blockIdx.z;
  const int q0 = qt * BM;
  const int nkt = qt + 1;

  const size_t plane = ((size_t)b * Hn + h) * Ln * En;
  const char* kbh = reinterpret_cast<const char*>(Khg + plane);
  const char* vbh = reinterpret_cast<const char*>(Vhg + plane);

  // ---- Q fragments (scale*log2e folded) ----
  uint32_t qh[4][4];
  {
    const __half* r0p = Qhg + plane + (size_t)(q0 + 16 * w + g) * En;
    const __half* r1p = r0p + 8 * En;
#pragma unroll
    for (int k = 0; k < 4; k++) {
      qh[k][0] = *reinterpret_cast<const uint32_t*>(r0p + 16 * k + 2 * tq);
      qh[k][1] = *reinterpret_cast<const uint32_t*>(r1p + 16 * k + 2 * tq);
      qh[k][2] = *reinterpret_cast<const uint32_t*>(r0p + 16 * k + 2 * tq + 8);
      qh[k][3] = *reinterpret_cast<const uint32_t*>(r1p + 16 * k + 2 * tq + 8);
    }
  }

  float o[8][4];
#pragma unroll
  for (int j = 0; j < 8; j++) { o[j][0] = o[j][1] = o[j][2] = o[j][3] = 0.0f; }
  float lacc[4] = {0.0f, 0.0f, 0.0f, 0.0f};  // row sums via ones-MMA
  const int row0 = q0 + 16 * w + g, row1 = row0 + 8;

  // ldmatrix lane bases
  const uint32_t kmb = (uint32_t)(lane & 7) * KSTRIDE + (uint32_t)(lane >> 3) * 16;
  const uint32_t vmb = (uint32_t)(lane & 15) * KSTRIDE + (uint32_t)(lane >> 4) * 16;

  // Diagonal-tile limit: warp w's rows end at 16w+15; j-block jb (keys 8jb..8jb+7)
  // is fully masked iff jb >= 2w+2.
  const int jb_dm_end = 2 * w + 2;

  stage_cp(sb, kbh, vbh, tid);
  asm volatile("cp.async.commit_group;" ::: "memory");

  for (int kt = 0; kt < nkt; kt++) {
    const uint32_t cbuf = sb + (uint32_t)(kt & 1) * BUFB;
    const bool pf = (kt + 1 < nkt);
    if (pf) {
      size_t rb = (size_t)(kt + 1) * 128 * 128;
      stage_cp(sb + (uint32_t)((kt + 1) & 1) * BUFB, kbh + rb, vbh + rb, tid);
      asm volatile("cp.async.commit_group;" ::: "memory");
      asm volatile("cp.async.wait_group 1;" ::: "memory");
    } else {
      asm volatile("cp.async.wait_group 0;" ::: "memory");
    }
    __syncthreads();

    const bool dm = (kt == nkt - 1);
    const int jb_end = dm ? jb_dm_end : 16;

    // ---- software-pipelined j-block loop ----
    uint32_t kf[2][8];   // double-buffered K fragments (one j-block each)
    uint32_t vf[16];     // V fragments for the current kp (loaded one stage early)
    uint32_t ph[4];      // P fragments for the current kp

    // prologue: K fragments for jb=0
    {
      const uint32_t a = cbuf + kmb;
      ldsm_x4(kf[0][0], kf[0][1], kf[0][2], kf[0][3], a);
      ldsm_x4(kf[0][4], kf[0][5], kf[0][6], kf[0][7], a + 64);
    }

#pragma unroll
    for (int jb = 0; jb < 16; jb++) {
      if (dm && jb >= jb_dm_end) break;
      const int cur = jb & 1;

      // (a) S-MMAs for jb from preloaded K fragments
      float cA[4] = {0.f, 0.f, 0.f, 0.f}, cB[4] = {0.f, 0.f, 0.f, 0.f};
      mma16816(cA, qh[0], kf[cur][0], kf[cur][1]);
      mma16816(cB, qh[1], kf[cur][2], kf[cur][3]);
      mma16816(cA, qh[2], kf[cur][4], kf[cur][5]);
      mma16816(cB, qh[3], kf[cur][6], kf[cur][7]);

      // (b) prefetch K for jb+1 — independent, fills the S-MMA shadow
      if (jb + 1 < jb_end) {
        const uint32_t a = cbuf + kmb + (uint32_t)(jb + 1) * (8 * KSTRIDE);
        ldsm_x4(kf[cur ^ 1][0], kf[cur ^ 1][1], kf[cur ^ 1][2], kf[cur ^ 1][3], a);
        ldsm_x4(kf[cur ^ 1][4], kf[cur ^ 1][5], kf[cur ^ 1][6], kf[cur ^ 1][7], a + 64);
      }

      // (c) on even stages prefetch V for kp=jb/2 — a full stage before use
      if (cur == 0) {
        const uint32_t vb = cbuf + TILE + vmb + (uint32_t)(jb >> 1) * (16 * KSTRIDE);
        ldsm_x4_t(vf[0], vf[1], vf[2], vf[3], vb);
        ldsm_x4_t(vf[4], vf[5], vf[6], vf[7], vb + 32);
        ldsm_x4_t(vf[8], vf[9], vf[10], vf[11], vb + 64);
        ldsm_x4_t(vf[12], vf[13], vf[14], vf[15], vb + 96);
      }

      // (d) softmax for jb
      float f0 = cA[0] + cB[0], f1 = cA[1] + cB[1];
      float f2 = cA[2] + cB[2], f3 = cA[3] + cB[3];
      if (dm) {
        int kb = kt * 128 + 8 * jb + 2 * tq;
        if (kb > row0) f0 = -1e30f;
        if (kb + 1 > row0) f1 = -1e30f;
        if (kb > row1) f2 = -1e30f;
        if (kb + 1 > row1) f3 = -1e30f;
      }
      ph[cur * 2 + 0] = packh(ex2f(f0), ex2f(f1));
      ph[cur * 2 + 1] = packh(ex2f(f2), ex2f(f3));

      // (e) on odd stages: ones-MMA row sums + PV burst (operands all in regs)
      if (cur == 1) {
        mma16816(lacc, ph, HONES, HONES);
#pragma unroll
        for (int j2 = 0; j2 < 4; j2++) {
          mma16816(o[2 * j2], ph, vf[4 * j2], vf[4 * j2 + 1]);
          mma16816(o[2 * j2 + 1], ph, vf[4 * j2 + 2], vf[4 * j2 + 3]);
        }
      }
    }
    __syncthreads();  // all warps done with cbuf before restage
  }

  // ---- epilogue: lacc holds exact row sums (no cross-lane reduce needed) ----
  const float i0 = 1.0f / lacc[0], i1 = 1.0f / lacc[2];
  float* r0p = O + ((size_t)(b * Ln + row0) * Hn + h) * En;
  float* r1p = r0p + 8 * (size_t)RS;
#pragma unroll
  for (int j = 0; j < 8; j++) {
    *reinterpret_cast<float2*>(r0p + 8 * j + 2 * tq) = make_float2(o[j][0] * i0, o[j][1] * i0);
    *reinterpret_cast<float2*>(r1p + 8 * j + 2 * tq) = make_float2(o[j][2] * i1, o[j][3] * i1);
  }
}

}  // namespace

extern "C" void kernel_launch(void* const* d_in, const int* in_sizes, int n_in,
                              void* d_out, int out_size) {
  (void)in_sizes; (void)n_in; (void)out_size;
  const float* Q = (const float*)d_in[0];
  const float* K = (const float*)d_in[1];
  const float* V = (const float*)d_in[2];
  float* O = (float*)d_out;

  prep<<<(Bn * Ln * Hn * (En / 4)) / 256, 256>>>(Q, K, V);

  cudaFuncSetAttribute(attn_mma, cudaFuncAttributeMaxDynamicSharedMemorySize, SMEM_TOTAL);
  dim3 grid(Ln / BM, Hn, Bn);  // (16 q-tiles, 16 heads, 2 batches)
  attn_mma<<<grid, 256, SMEM_TOTAL>>>(O);
}

// round 14
// speedup vs baseline: 1.0286x; 1.0286x over previous
#include <cuda_runtime.h>
#include <cuda_fp16.h>
#include <cstdint>

namespace {

constexpr int Bn = 2, Ln = 2048, Hn = 16, En = 64;
constexpr int BM = 128, BN = 128;
constexpr int RS = Hn * En;  // 1024 floats between seq positions in Q/O

constexpr uint32_t KSTRIDE = 144;            // 64 fp16 = 128B + 16B pad
constexpr uint32_t TILE = 128 * KSTRIDE;     // 18432 B (128 rows)
constexpr uint32_t BUFB = 2 * TILE;          // Kh, Vh
constexpr uint32_t SMEM_TOTAL = 2 * BUFB;    // 73728 B -> 3 CTAs/SM (216KB)

constexpr float QSCALE = 0.125f * 1.44269504f;  // (1/sqrt(64)) * log2(e), folded into Q
constexpr uint32_t HONES = 0x3C003C00u;         // fp16x2 {1.0, 1.0}

// Preprocessed fp16 operands, [B, H, L, E] layout (rows of 128B).
constexpr size_t NE = (size_t)Bn * Hn * Ln * En;
__device__ __half Qhg[NE];
__device__ __half Khg[NE];
__device__ __half Vhg[NE];

__device__ __forceinline__ uint32_t packh(float lo, float hi) {
  uint32_t r;
  asm("cvt.rn.f16x2.f32 %0, %1, %2;" : "=r"(r) : "f"(hi), "f"(lo));
  return r;
}
__device__ __forceinline__ float ex2f(float x) {
  float r;
  asm("ex2.approx.f32 %0, %1;" : "=f"(r) : "f"(x));
  return r;
}

__device__ __forceinline__ void mma16816(float (&c)[4], const uint32_t (&a)[4],
                                         uint32_t b0, uint32_t b1) {
  asm volatile(
      "mma.sync.aligned.m16n8k16.row.col.f32.f16.f16.f32 "
      "{%0,%1,%2,%3}, {%4,%5,%6,%7}, {%8,%9}, {%0,%1,%2,%3};"
      : "+f"(c[0]), "+f"(c[1]), "+f"(c[2]), "+f"(c[3])
      : "r"(a[0]), "r"(a[1]), "r"(a[2]), "r"(a[3]), "r"(b0), "r"(b1));
}
__device__ __forceinline__ void ldsm_x4(uint32_t& r0, uint32_t& r1, uint32_t& r2, uint32_t& r3,
                                        uint32_t addr) {
  asm volatile("ldmatrix.sync.aligned.m8n8.x4.shared.b16 {%0,%1,%2,%3}, [%4];"
               : "=r"(r0), "=r"(r1), "=r"(r2), "=r"(r3) : "r"(addr));
}
__device__ __forceinline__ void ldsm_x4_t(uint32_t& r0, uint32_t& r1, uint32_t& r2, uint32_t& r3,
                                          uint32_t addr) {
  asm volatile("ldmatrix.sync.aligned.m8n8.x4.trans.shared.b16 {%0,%1,%2,%3}, [%4];"
               : "=r"(r0), "=r"(r1), "=r"(r2), "=r"(r3) : "r"(addr));
}
__device__ __forceinline__ uint32_t smem_u32(const void* p) {
  uint32_t a;
  asm("{ .reg .u64 t; cvta.to.shared.u64 t, %1; cvt.u32.u64 %0, t; }" : "=r"(a) : "l"(p));
  return a;
}

// ---------------- prep: fp32 [B,L,H,E] -> fp16 [B,H,L,E] ----------------
__global__ void __launch_bounds__(256)
prep(const float* __restrict__ Q, const float* __restrict__ K, const float* __restrict__ V) {
  uint32_t g = blockIdx.x * 256u + threadIdx.x;
  uint32_t e4 = g & 15u, h = (g >> 4) & 15u, l = (g >> 8) & 2047u, b = g >> 19;
  size_t si = (((size_t)b * Ln + l) * Hn + h) * En + 4 * e4;
  size_t di = (((size_t)b * Hn + h) * Ln + l) * En + 4 * e4;

  float4 q = *reinterpret_cast<const float4*>(Q + si);
  float4 k = *reinterpret_cast<const float4*>(K + si);
  float4 v = *reinterpret_cast<const float4*>(V + si);

  q.x *= QSCALE; q.y *= QSCALE; q.z *= QSCALE; q.w *= QSCALE;
  *reinterpret_cast<__half2*>(&Qhg[di]) =
      __halves2half2(__float2half_rn(q.x), __float2half_rn(q.y));
  *reinterpret_cast<__half2*>(&Qhg[di + 2]) =
      __halves2half2(__float2half_rn(q.z), __float2half_rn(q.w));

  *reinterpret_cast<__half2*>(&Khg[di]) =
      __halves2half2(__float2half_rn(k.x), __float2half_rn(k.y));
  *reinterpret_cast<__half2*>(&Khg[di + 2]) =
      __halves2half2(__float2half_rn(k.z), __float2half_rn(k.w));

  *reinterpret_cast<__half2*>(&Vhg[di]) =
      __halves2half2(__float2half_rn(v.x), __float2half_rn(v.y));
  *reinterpret_cast<__half2*>(&Vhg[di + 2]) =
      __halves2half2(__float2half_rn(v.z), __float2half_rn(v.w));
}

// ---------------- attention ----------------
// Stage one 128-key tile set (Kh, Vh) into smem via cp.async (16 x 16B per thread).
__device__ __forceinline__ void stage_cp(uint32_t sdst, const char* kh, const char* vh, int tid) {
#pragma unroll
  for (int i = 0; i < 16; i++) {
    const int t = i >> 3;  // 0=Kh 1=Vh
    int idx = (i & 7) * 128 + tid;   // 0..1023
    int r = idx >> 3, c = idx & 7;
    const char* src = (t == 0 ? kh : vh) + r * 128 + c * 16;
    uint32_t dst = sdst + (uint32_t)t * TILE + (uint32_t)r * KSTRIDE + 16u * c;
    asm volatile("cp.async.cg.shared.global [%0], [%1], 16;" :: "r"(dst), "l"(src));
  }
}

__global__ void __launch_bounds__(128, 3)
attn_mma(float* __restrict__ O) {
  extern __shared__ __align__(16) char smem[];
  const uint32_t sb = smem_u32(smem);

  const int tid = threadIdx.x;
  const int w = tid >> 5, lane = tid & 31;  // 4 warps, each m32
  const int g = lane >> 2, tq = lane & 3;

  const int qt = (int)gridDim.x - 1 - (int)blockIdx.x;  // heavy tiles first
  const int h = blockIdx.y, b = blockIdx.z;
  const int q0 = qt * BM;
  const int nkt = qt + 1;

  const size_t plane = ((size_t)b * Hn + h) * Ln * En;
  const char* kbh = reinterpret_cast<const char*>(Khg + plane);
  const char* vbh = reinterpret_cast<const char*>(Vhg + plane);

  // ---- Q fragments for rows 32w..32w+31 (scale*log2e folded) ----
  uint32_t qL[4][4], qH[4][4];
  {
    const __half* r0p = Qhg + plane + (size_t)(q0 + 32 * w + g) * En;
    const __half* r1p = r0p + 8 * En;
    const __half* r2p = r0p + 16 * En;
    const __half* r3p = r0p + 24 * En;
#pragma unroll
    for (int k = 0; k < 4; k++) {
      qL[k][0] = *reinterpret_cast<const uint32_t*>(r0p + 16 * k + 2 * tq);
      qL[k][1] = *reinterpret_cast<const uint32_t*>(r1p + 16 * k + 2 * tq);
      qL[k][2] = *reinterpret_cast<const uint32_t*>(r0p + 16 * k + 2 * tq + 8);
      qL[k][3] = *reinterpret_cast<const uint32_t*>(r1p + 16 * k + 2 * tq + 8);
      qH[k][0] = *reinterpret_cast<const uint32_t*>(r2p + 16 * k + 2 * tq);
      qH[k][1] = *reinterpret_cast<const uint32_t*>(r3p + 16 * k + 2 * tq);
      qH[k][2] = *reinterpret_cast<const uint32_t*>(r2p + 16 * k + 2 * tq + 8);
      qH[k][3] = *reinterpret_cast<const uint32_t*>(r3p + 16 * k + 2 * tq + 8);
    }
  }

  float oL[8][4], oH[8][4];
#pragma unroll
  for (int j = 0; j < 8; j++) {
    oL[j][0] = oL[j][1] = oL[j][2] = oL[j][3] = 0.0f;
    oH[j][0] = oH[j][1] = oH[j][2] = oH[j][3] = 0.0f;
  }
  float laccL[4] = {0.f, 0.f, 0.f, 0.f}, laccH[4] = {0.f, 0.f, 0.f, 0.f};
  const int row0 = q0 + 32 * w + g;
  const int row1 = row0 + 8, row2 = row0 + 16, row3 = row0 + 24;

  // ldmatrix lane bases
  const uint32_t kmb = (uint32_t)(lane & 7) * KSTRIDE + (uint32_t)(lane >> 3) * 16;
  const uint32_t vmb = (uint32_t)(lane & 15) * KSTRIDE + (uint32_t)(lane >> 4) * 16;

  // Diagonal tile: kp (keys 16kp..16kp+15) fully masked iff kp >= 2w+2.
  const int kp_dm_end = 2 * w + 2;

  stage_cp(sb, kbh, vbh, tid);
  asm volatile("cp.async.commit_group;" ::: "memory");

  for (int kt = 0; kt < nkt; kt++) {
    const uint32_t cbuf = sb + (uint32_t)(kt & 1) * BUFB;
    const bool pf = (kt + 1 < nkt);
    if (pf) {
      size_t rb = (size_t)(kt + 1) * 128 * 128;
      stage_cp(sb + (uint32_t)((kt + 1) & 1) * BUFB, kbh + rb, vbh + rb, tid);
      asm volatile("cp.async.commit_group;" ::: "memory");
      asm volatile("cp.async.wait_group 1;" ::: "memory");
    } else {
      asm volatile("cp.async.wait_group 0;" ::: "memory");
    }
    __syncthreads();

    const bool dm = (kt == nkt - 1);

#pragma unroll
    for (int kp = 0; kp < 8; kp++) {  // kp covers S j-blocks 2kp, 2kp+1 (16 keys)
      if (dm && kp >= kp_dm_end) break;

      uint32_t phL[4], phH[4];
#pragma unroll
      for (int jj = 0; jj < 2; jj++) {
        const int j = 2 * kp + jj;
        const uint32_t a = cbuf + kmb + (uint32_t)j * (8 * KSTRIDE);
        uint32_t b0, b1, b2, b3, b4, b5, b6, b7;
        ldsm_x4(b0, b1, b2, b3, a);        // k-steps 0,1
        ldsm_x4(b4, b5, b6, b7, a + 64);   // k-steps 2,3
        // Two independent 4-deep chains (lo rows / hi rows) share every B fragment.
        float cL[4] = {0.f, 0.f, 0.f, 0.f}, cH[4] = {0.f, 0.f, 0.f, 0.f};
        mma16816(cL, qL[0], b0, b1);
        mma16816(cH, qH[0], b0, b1);
        mma16816(cL, qL[1], b2, b3);
        mma16816(cH, qH[1], b2, b3);
        mma16816(cL, qL[2], b4, b5);
        mma16816(cH, qH[2], b4, b5);
        mma16816(cL, qL[3], b6, b7);
        mma16816(cH, qH[3], b6, b7);

        float f0 = cL[0], f1 = cL[1], f2 = cL[2], f3 = cL[3];
        float g0 = cH[0], g1 = cH[1], g2 = cH[2], g3 = cH[3];
        if (dm) {
          int kb = kt * 128 + 8 * j + 2 * tq;
          if (kb > row0) f0 = -1e30f;
          if (kb + 1 > row0) f1 = -1e30f;
          if (kb > row1) f2 = -1e30f;
          if (kb + 1 > row1) f3 = -1e30f;
          if (kb > row2) g0 = -1e30f;
          if (kb + 1 > row2) g1 = -1e30f;
          if (kb > row3) g2 = -1e30f;
          if (kb + 1 > row3) g3 = -1e30f;
        }
        phL[jj * 2 + 0] = packh(ex2f(f0), ex2f(f1));
        phL[jj * 2 + 1] = packh(ex2f(f2), ex2f(f3));
        phH[jj * 2 + 0] = packh(ex2f(g0), ex2f(g1));
        phH[jj * 2 + 1] = packh(ex2f(g2), ex2f(g3));
      }

      // Row sums on the tensor pipe (ones B): all output cols equal the row sum.
      mma16816(laccL, phL, HONES, HONES);
      mma16816(laccH, phH, HONES, HONES);

      // PV: each V fragment pair feeds BOTH row halves (1 wavefront per MMA).
#pragma unroll
      for (int j2 = 0; j2 < 4; j2++) {
        uint32_t a = cbuf + TILE + vmb + (uint32_t)kp * (16 * KSTRIDE) + 32u * j2;
        uint32_t v0, v1, v2, v3;
        ldsm_x4_t(v0, v1, v2, v3, a);
        mma16816(oL[2 * j2], phL, v0, v1);
        mma16816(oH[2 * j2], phH, v0, v1);
        mma16816(oL[2 * j2 + 1], phL, v2, v3);
        mma16816(oH[2 * j2 + 1], phH, v2, v3);
      }
    }
    __syncthreads();  // all warps done with cbuf before restage
  }

  // ---- epilogue: lacc holds exact row sums; 4 output rows per lane ----
  const float iL0 = 1.0f / laccL[0], iL1 = 1.0f / laccL[2];
  const float iH0 = 1.0f / laccH[0], iH1 = 1.0f / laccH[2];
  float* r0p = O + ((size_t)(b * Ln + row0) * Hn + h) * En;
  float* r1p = r0p + 8 * (size_t)RS;
  float* r2p = r0p + 16 * (size_t)RS;
  float* r3p = r0p + 24 * (size_t)RS;
#pragma unroll
  for (int j = 0; j < 8; j++) {
    *reinterpret_cast<float2*>(r0p + 8 * j + 2 * tq) =
        make_float2(oL[j][0] * iL0, oL[j][1] * iL0);
    *reinterpret_cast<float2*>(r1p + 8 * j + 2 * tq) =
        make_float2(oL[j][2] * iL1, oL[j][3] * iL1);
    *reinterpret_cast<float2*>(r2p + 8 * j + 2 * tq) =
        make_float2(oH[j][0] * iH0, oH[j][1] * iH0);
    *reinterpret_cast<float2*>(r3p + 8 * j + 2 * tq) =
        make_float2(oH[j][2] * iH1, oH[j][3] * iH1);
  }
}

}  // namespace

extern "C" void kernel_launch(void* const* d_in, const int* in_sizes, int n_in,
                              void* d_out, int out_size) {
  (void)in_sizes; (void)n_in; (void)out_size;
  const float* Q = (const float*)d_in[0];
  const float* K = (const float*)d_in[1];
  const float* V = (const float*)d_in[2];
  float* O = (float*)d_out;

  prep<<<(Bn * Ln * Hn * (En / 4)) / 256, 256>>>(Q, K, V);

  cudaFuncSetAttribute(attn_mma, cudaFuncAttributeMaxDynamicSharedMemorySize, SMEM_TOTAL);
  dim3 grid(Ln / BM, Hn, Bn);  // (16 q-tiles, 16 heads, 2 batches)
  attn_mma<<<grid, 128, SMEM_TOTAL>>>(O);
}

// round 15
// speedup vs baseline: 1.1235x; 1.0923x over previous
#include <cuda_runtime.h>
#include <cuda_fp16.h>
#include <cstdint>

namespace {

constexpr int Bn = 2, Ln = 2048, Hn = 16, En = 64;
constexpr int BM = 128, BN = 128;
constexpr int RS = Hn * En;  // 1024 floats between seq positions in Q/O

constexpr uint32_t KSTRIDE = 144;            // 64 fp16 = 128B + 16B pad
constexpr uint32_t TILE = 128 * KSTRIDE;     // 18432 B (128 rows)
constexpr uint32_t BUFB = 2 * TILE;          // Kh, Vh
constexpr uint32_t SMEM_TOTAL = 2 * BUFB;    // 73728 B -> 2 CTAs/SM

constexpr float QSCALE = 0.125f * 1.44269504f;  // (1/sqrt(64)) * log2(e), folded into Q
constexpr uint32_t HONES = 0x3C003C00u;         // fp16x2 {1.0, 1.0}

// Preprocessed fp16 operands, [B, H, L, E] layout (rows of 128B).
constexpr size_t NE = (size_t)Bn * Hn * Ln * En;
__device__ __half Qhg[NE];
__device__ __half Khg[NE];
__device__ __half Vhg[NE];

__device__ __forceinline__ uint32_t packh(float lo, float hi) {
  uint32_t r;
  asm("cvt.rn.f16x2.f32 %0, %1, %2;" : "=r"(r) : "f"(hi), "f"(lo));
  return r;
}
__device__ __forceinline__ float ex2f(float x) {
  float r;
  asm("ex2.approx.f32 %0, %1;" : "=f"(r) : "f"(x));
  return r;
}

__device__ __forceinline__ void mma16816(float (&c)[4], const uint32_t (&a)[4],
                                         uint32_t b0, uint32_t b1) {
  asm volatile(
      "mma.sync.aligned.m16n8k16.row.col.f32.f16.f16.f32 "
      "{%0,%1,%2,%3}, {%4,%5,%6,%7}, {%8,%9}, {%0,%1,%2,%3};"
      : "+f"(c[0]), "+f"(c[1]), "+f"(c[2]), "+f"(c[3])
      : "r"(a[0]), "r"(a[1]), "r"(a[2]), "r"(a[3]), "r"(b0), "r"(b1));
}
__device__ __forceinline__ void ldsm_x4(uint32_t& r0, uint32_t& r1, uint32_t& r2, uint32_t& r3,
                                        uint32_t addr) {
  asm volatile("ldmatrix.sync.aligned.m8n8.x4.shared.b16 {%0,%1,%2,%3}, [%4];"
               : "=r"(r0), "=r"(r1), "=r"(r2), "=r"(r3) : "r"(addr));
}
__device__ __forceinline__ void ldsm_x4_t(uint32_t& r0, uint32_t& r1, uint32_t& r2, uint32_t& r3,
                                          uint32_t addr) {
  asm volatile("ldmatrix.sync.aligned.m8n8.x4.trans.shared.b16 {%0,%1,%2,%3}, [%4];"
               : "=r"(r0), "=r"(r1), "=r"(r2), "=r"(r3) : "r"(addr));
}
__device__ __forceinline__ uint32_t smem_u32(const void* p) {
  uint32_t a;
  asm("{ .reg .u64 t; cvta.to.shared.u64 t, %1; cvt.u32.u64 %0, t; }" : "=r"(a) : "l"(p));
  return a;
}

// ---------------- prep: fp32 [B,L,H,E] -> fp16 [B,H,L,E] ----------------
__global__ void __launch_bounds__(256)
prep(const float* __restrict__ Q, const float* __restrict__ K, const float* __restrict__ V) {
  uint32_t g = blockIdx.x * 256u + threadIdx.x;
  uint32_t e4 = g & 15u, h = (g >> 4) & 15u, l = (g >> 8) & 2047u, b = g >> 19;
  size_t si = (((size_t)b * Ln + l) * Hn + h) * En + 4 * e4;
  size_t di = (((size_t)b * Hn + h) * Ln + l) * En + 4 * e4;

  float4 q = *reinterpret_cast<const float4*>(Q + si);
  float4 k = *reinterpret_cast<const float4*>(K + si);
  float4 v = *reinterpret_cast<const float4*>(V + si);

  q.x *= QSCALE; q.y *= QSCALE; q.z *= QSCALE; q.w *= QSCALE;
  *reinterpret_cast<__half2*>(&Qhg[di]) =
      __halves2half2(__float2half_rn(q.x), __float2half_rn(q.y));
  *reinterpret_cast<__half2*>(&Qhg[di + 2]) =
      __halves2half2(__float2half_rn(q.z), __float2half_rn(q.w));

  *reinterpret_cast<__half2*>(&Khg[di]) =
      __halves2half2(__float2half_rn(k.x), __float2half_rn(k.y));
  *reinterpret_cast<__half2*>(&Khg[di + 2]) =
      __halves2half2(__float2half_rn(k.z), __float2half_rn(k.w));

  *reinterpret_cast<__half2*>(&Vhg[di]) =
      __halves2half2(__float2half_rn(v.x), __float2half_rn(v.y));
  *reinterpret_cast<__half2*>(&Vhg[di + 2]) =
      __halves2half2(__float2half_rn(v.z), __float2half_rn(v.w));
}

// ---------------- attention ----------------
__device__ __forceinline__ void stage_cp(uint32_t sdst, const char* kh, const char* vh, int tid) {
#pragma unroll
  for (int i = 0; i < 8; i++) {
    const int t = i >> 2;  // 0=Kh 1=Vh
    int r = (tid >> 3) + 32 * (i & 3);
    int c = tid & 7;
    const char* src = (t == 0 ? kh : vh) + r * 128 + c * 16;
    uint32_t dst = sdst + (uint32_t)t * TILE + (uint32_t)r * KSTRIDE + 16u * c;
    asm volatile("cp.async.cg.shared.global [%0], [%1], 16;" :: "r"(dst), "l"(src));
  }
}

__global__ void __launch_bounds__(256, 2)
attn_mma(float* __restrict__ O) {
  extern __shared__ __align__(16) char smem[];
  const uint32_t sb = smem_u32(smem);

  const int tid = threadIdx.x;
  const int w = tid >> 5, lane = tid & 31;
  const int g = lane >> 2, tq = lane & 3;

  const int qt = (int)gridDim.x - 1 - (int)blockIdx.x;  // heavy tiles first
  const int h = blockIdx.y, b = blockIdx.z;
  const int q0 = qt * BM;
  const int nkt = qt + 1;

  const size_t plane = ((size_t)b * Hn + h) * Ln * En;
  const char* kbh = reinterpret_cast<const char*>(Khg + plane);
  const char* vbh = reinterpret_cast<const char*>(Vhg + plane);

  // ---- Q fragments (scale*log2e folded) ----
  uint32_t qh[4][4];
  {
    const __half* r0p = Qhg + plane + (size_t)(q0 + 16 * w + g) * En;
    const __half* r1p = r0p + 8 * En;
#pragma unroll
    for (int k = 0; k < 4; k++) {
      qh[k][0] = *reinterpret_cast<const uint32_t*>(r0p + 16 * k + 2 * tq);
      qh[k][1] = *reinterpret_cast<const uint32_t*>(r1p + 16 * k + 2 * tq);
      qh[k][2] = *reinterpret_cast<const uint32_t*>(r0p + 16 * k + 2 * tq + 8);
      qh[k][3] = *reinterpret_cast<const uint32_t*>(r1p + 16 * k + 2 * tq + 8);
    }
  }

  float o[8][4];
#pragma unroll
  for (int j = 0; j < 8; j++) { o[j][0] = o[j][1] = o[j][2] = o[j][3] = 0.0f; }
  float lacc[4] = {0.0f, 0.0f, 0.0f, 0.0f};  // row sums via ones-MMA
  const int row0 = q0 + 16 * w + g, row1 = row0 + 8;

  // ldmatrix lane bases
  const uint32_t kmb = (uint32_t)(lane & 7) * KSTRIDE + (uint32_t)(lane >> 3) * 16;
  const uint32_t vmb = (uint32_t)(lane & 15) * KSTRIDE + (uint32_t)(lane >> 4) * 16;

  stage_cp(sb, kbh, vbh, tid);
  asm volatile("cp.async.commit_group;" ::: "memory");

  for (int kt = 0; kt < nkt; kt++) {
    const uint32_t cbuf = sb + (uint32_t)(kt & 1) * BUFB;
    const bool pf = (kt + 1 < nkt);
    if (pf) {
      size_t rb = (size_t)(kt + 1) * 128 * 128;
      stage_cp(sb + (uint32_t)((kt + 1) & 1) * BUFB, kbh + rb, vbh + rb, tid);
      asm volatile("cp.async.commit_group;" ::: "memory");
      asm volatile("cp.async.wait_group 1;" ::: "memory");
    } else {
      asm volatile("cp.async.wait_group 0;" ::: "memory");
    }
    __syncthreads();

    if (kt < nkt - 1) {
      // ================= non-diagonal tile: 2-stage software pipeline =================
      uint32_t kf0[8], kf1[8];   // double-buffered K fragments
      uint32_t vf[16];           // V fragments for current kp (loaded 1 stage early)
      uint32_t ph[4];            // P fragments (completed 1 stage late)
      float cb0[8], cb1[8];      // double-buffered raw S accumulators (cA|cB)

      // prologue: K fragments for jb=0
      ldsm_x4(kf0[0], kf0[1], kf0[2], kf0[3], cbuf + kmb);
      ldsm_x4(kf0[4], kf0[5], kf0[6], kf0[7], cbuf + kmb + 64);

#pragma unroll
      for (int jb = 0; jb < 16; jb++) {
        const int cur = jb & 1;
        uint32_t* kfc = cur ? kf1 : kf0;
        float* cc = cur ? cb1 : cb0;

        // (1) S-MMAs(jb): operands preloaded last stage; results consumed next stage
        cc[0] = cc[1] = cc[2] = cc[3] = 0.f;
        cc[4] = cc[5] = cc[6] = cc[7] = 0.f;
        mma16816(*reinterpret_cast<float(*)[4]>(cc), qh[0], kfc[0], kfc[1]);
        mma16816(*reinterpret_cast<float(*)[4]>(cc + 4), qh[1], kfc[2], kfc[3]);
        mma16816(*reinterpret_cast<float(*)[4]>(cc), qh[2], kfc[4], kfc[5]);
        mma16816(*reinterpret_cast<float(*)[4]>(cc + 4), qh[3], kfc[6], kfc[7]);

        // (2) prefetch K(jb+1)
        if (jb + 1 < 16) {
          uint32_t* kfn = cur ? kf0 : kf1;
          const uint32_t a = cbuf + kmb + (uint32_t)(jb + 1) * (8 * KSTRIDE);
          ldsm_x4(kfn[0], kfn[1], kfn[2], kfn[3], a);
          ldsm_x4(kfn[4], kfn[5], kfn[6], kfn[7], a + 64);
        }

        // (3) odd stages: prefetch V for kp=jb>>1 (consumed at stage jb+1)
        if (cur == 1) {
          const uint32_t vb = cbuf + TILE + vmb + (uint32_t)(jb >> 1) * (16 * KSTRIDE);
          ldsm_x4_t(vf[0], vf[1], vf[2], vf[3], vb);
          ldsm_x4_t(vf[4], vf[5], vf[6], vf[7], vb + 32);
          ldsm_x4_t(vf[8], vf[9], vf[10], vf[11], vb + 64);
          ldsm_x4_t(vf[12], vf[13], vf[14], vf[15], vb + 96);
        }

        // (4) softmax(jb-1): overlaps the tensor pipe working on S-MMAs(jb)
        if (jb >= 1) {
          const float* cp = (cur == 1) ? cb0 : cb1;
          const int pp = (jb - 1) & 1;
          ph[pp * 2 + 0] = packh(ex2f(cp[0] + cp[4]), ex2f(cp[1] + cp[5]));
          ph[pp * 2 + 1] = packh(ex2f(cp[2] + cp[6]), ex2f(cp[3] + cp[7]));
        }

        // (5) even stages >= 2: PV burst for kp=(jb-2)/2 (ph, vf both ready)
        if (cur == 0 && jb >= 2) {
          mma16816(lacc, ph, HONES, HONES);
#pragma unroll
          for (int j2 = 0; j2 < 4; j2++) {
            mma16816(o[2 * j2], ph, vf[4 * j2], vf[4 * j2 + 1]);
            mma16816(o[2 * j2 + 1], ph, vf[4 * j2 + 2], vf[4 * j2 + 3]);
          }
        }
      }
      // drain: softmax(15) then PV(kp=7)
      ph[2] = packh(ex2f(cb1[0] + cb1[4]), ex2f(cb1[1] + cb1[5]));
      ph[3] = packh(ex2f(cb1[2] + cb1[6]), ex2f(cb1[3] + cb1[7]));
      mma16816(lacc, ph, HONES, HONES);
#pragma unroll
      for (int j2 = 0; j2 < 4; j2++) {
        mma16816(o[2 * j2], ph, vf[4 * j2], vf[4 * j2 + 1]);
        mma16816(o[2 * j2 + 1], ph, vf[4 * j2 + 2], vf[4 * j2 + 3]);
      }
    } else {
      // ================= diagonal tile: simple masked kp loop =================
#pragma unroll
      for (int kp = 0; kp < 8; kp++) {
        if (kp > w) break;
        uint32_t ph[4];
#pragma unroll
        for (int jj = 0; jj < 2; jj++) {
          const int j = 2 * kp + jj;
          const uint32_t a = cbuf + kmb + (uint32_t)j * (8 * KSTRIDE);
          uint32_t b0, b1, b2, b3, b4, b5, b6, b7;
          ldsm_x4(b0, b1, b2, b3, a);
          ldsm_x4(b4, b5, b6, b7, a + 64);
          float cA[4] = {0.f, 0.f, 0.f, 0.f}, cB[4] = {0.f, 0.f, 0.f, 0.f};
          mma16816(cA, qh[0], b0, b1);
          mma16816(cB, qh[1], b2, b3);
          mma16816(cA, qh[2], b4, b5);
          mma16816(cB, qh[3], b6, b7);

          float f0 = cA[0] + cB[0], f1 = cA[1] + cB[1];
          float f2 = cA[2] + cB[2], f3 = cA[3] + cB[3];
          int kb = kt * 128 + 8 * j + 2 * tq;
          if (kb > row0) f0 = -1e30f;
          if (kb + 1 > row0) f1 = -1e30f;
          if (kb > row1) f2 = -1e30f;
          if (kb + 1 > row1) f3 = -1e30f;
          ph[jj * 2 + 0] = packh(ex2f(f0), ex2f(f1));
          ph[jj * 2 + 1] = packh(ex2f(f2), ex2f(f3));
        }
        mma16816(lacc, ph, HONES, HONES);
#pragma unroll
        for (int j2 = 0; j2 < 4; j2++) {
          uint32_t a = cbuf + TILE + vmb + (uint32_t)kp * (16 * KSTRIDE) + 32u * j2;
          uint32_t v0, v1, v2, v3;
          ldsm_x4_t(v0, v1, v2, v3, a);
          mma16816(o[2 * j2], ph, v0, v1);
          mma16816(o[2 * j2 + 1], ph, v2, v3);
        }
      }
    }
    __syncthreads();  // all warps done with cbuf before restage
  }

  // ---- epilogue: lacc holds exact row sums (no cross-lane reduce needed) ----
  const float i0 = 1.0f / lacc[0], i1 = 1.0f / lacc[2];
  float* r0p = O + ((size_t)(b * Ln + row0) * Hn + h) * En;
  float* r1p = r0p + 8 * (size_t)RS;
#pragma unroll
  for (int j = 0; j < 8; j++) {
    *reinterpret_cast<float2*>(r0p + 8 * j + 2 * tq) = make_float2(o[j][0] * i0, o[j][1] * i0);
    *reinterpret_cast<float2*>(r1p + 8 * j + 2 * tq) = make_float2(o[j][2] * i1, o[j][3] * i1);
  }
}

}  // namespace

extern "C" void kernel_launch(void* const* d_in, const int* in_sizes, int n_in,
                              void* d_out, int out_size) {
  (void)in_sizes; (void)n_in; (void)out_size;
  const float* Q = (const float*)d_in[0];
  const float* K = (const float*)d_in[1];
  const float* V = (const float*)d_in[2];
  float* O = (float*)d_out;

  prep<<<(Bn * Ln * Hn * (En / 4)) / 256, 256>>>(Q, K, V);

  cudaFuncSetAttribute(attn_mma, cudaFuncAttributeMaxDynamicSharedMemorySize, SMEM_TOTAL);
  dim3 grid(Ln / BM, Hn, Bn);  // (16 q-tiles, 16 heads, 2 batches)
  attn_mma<<<grid, 256, SMEM_TOTAL>>>(O);
}

// round 16
// speedup vs baseline: 1.1498x; 1.0234x over previous
#include <cuda_runtime.h>
#include <cuda_fp16.h>
#include <cstdint>

namespace {

constexpr int Bn = 2, Ln = 2048, Hn = 16, En = 64;
constexpr int BM = 128, BN = 128;
constexpr int RS = Hn * En;  // 1024 floats between seq positions in Q/O

constexpr uint32_t KSTRIDE = 144;            // 64 fp16 = 128B + 16B pad
constexpr uint32_t TILE = 128 * KSTRIDE;     // 18432 B (128 rows)
constexpr uint32_t BUFB = 2 * TILE;          // Kh, Vh
constexpr uint32_t SMEM_TOTAL = 2 * BUFB;    // 73728 B -> 2 CTAs/SM

constexpr float QSCALE = 0.125f * 1.44269504f;  // (1/sqrt(64)) * log2(e), folded into Q
constexpr uint32_t HONES = 0x3C003C00u;         // fp16x2 {1.0, 1.0}

// Preprocessed fp16 operands, [B, H, L, E] layout (rows of 128B).
constexpr size_t NE = (size_t)Bn * Hn * Ln * En;
__device__ __half Qhg[NE];
__device__ __half Khg[NE];
__device__ __half Vhg[NE];

__device__ __forceinline__ uint32_t packh(float lo, float hi) {
  uint32_t r;
  asm("cvt.rn.f16x2.f32 %0, %1, %2;" : "=r"(r) : "f"(hi), "f"(lo));
  return r;
}
// 2^x on both fp16 halves in ONE MUFU pass (replaces two f32 ex2 + keeps pack count).
__device__ __forceinline__ uint32_t ex2h2(uint32_t x) {
  uint32_t r;
  asm("ex2.approx.f16x2 %0, %1;" : "=r"(r) : "r"(x));
  return r;
}

__device__ __forceinline__ void mma16816(float (&c)[4], const uint32_t (&a)[4],
                                         uint32_t b0, uint32_t b1) {
  asm volatile(
      "mma.sync.aligned.m16n8k16.row.col.f32.f16.f16.f32 "
      "{%0,%1,%2,%3}, {%4,%5,%6,%7}, {%8,%9}, {%0,%1,%2,%3};"
      : "+f"(c[0]), "+f"(c[1]), "+f"(c[2]), "+f"(c[3])
      : "r"(a[0]), "r"(a[1]), "r"(a[2]), "r"(a[3]), "r"(b0), "r"(b1));
}
__device__ __forceinline__ void ldsm_x4(uint32_t& r0, uint32_t& r1, uint32_t& r2, uint32_t& r3,
                                        uint32_t addr) {
  asm volatile("ldmatrix.sync.aligned.m8n8.x4.shared.b16 {%0,%1,%2,%3}, [%4];"
               : "=r"(r0), "=r"(r1), "=r"(r2), "=r"(r3) : "r"(addr));
}
__device__ __forceinline__ void ldsm_x4_t(uint32_t& r0, uint32_t& r1, uint32_t& r2, uint32_t& r3,
                                          uint32_t addr) {
  asm volatile("ldmatrix.sync.aligned.m8n8.x4.trans.shared.b16 {%0,%1,%2,%3}, [%4];"
               : "=r"(r0), "=r"(r1), "=r"(r2), "=r"(r3) : "r"(addr));
}
__device__ __forceinline__ uint32_t smem_u32(const void* p) {
  uint32_t a;
  asm("{ .reg .u64 t; cvta.to.shared.u64 t, %1; cvt.u32.u64 %0, t; }" : "=r"(a) : "l"(p));
  return a;
}

// ---------------- prep: fp32 [B,L,H,E] -> fp16 [B,H,L,E] ----------------
__global__ void __launch_bounds__(256)
prep(const float* __restrict__ Q, const float* __restrict__ K, const float* __restrict__ V) {
  uint32_t g = blockIdx.x * 256u + threadIdx.x;
  uint32_t e4 = g & 15u, h = (g >> 4) & 15u, l = (g >> 8) & 2047u, b = g >> 19;
  size_t si = (((size_t)b * Ln + l) * Hn + h) * En + 4 * e4;
  size_t di = (((size_t)b * Hn + h) * Ln + l) * En + 4 * e4;

  float4 q = *reinterpret_cast<const float4*>(Q + si);
  float4 k = *reinterpret_cast<const float4*>(K + si);
  float4 v = *reinterpret_cast<const float4*>(V + si);

  q.x *= QSCALE; q.y *= QSCALE; q.z *= QSCALE; q.w *= QSCALE;
  *reinterpret_cast<__half2*>(&Qhg[di]) =
      __halves2half2(__float2half_rn(q.x), __float2half_rn(q.y));
  *reinterpret_cast<__half2*>(&Qhg[di + 2]) =
      __halves2half2(__float2half_rn(q.z), __float2half_rn(q.w));

  *reinterpret_cast<__half2*>(&Khg[di]) =
      __halves2half2(__float2half_rn(k.x), __float2half_rn(k.y));
  *reinterpret_cast<__half2*>(&Khg[di + 2]) =
      __halves2half2(__float2half_rn(k.z), __float2half_rn(k.w));

  *reinterpret_cast<__half2*>(&Vhg[di]) =
      __halves2half2(__float2half_rn(v.x), __float2half_rn(v.y));
  *reinterpret_cast<__half2*>(&Vhg[di + 2]) =
      __halves2half2(__float2half_rn(v.z), __float2half_rn(v.w));
}

// ---------------- attention ----------------
__device__ __forceinline__ void stage_cp(uint32_t sdst, const char* kh, const char* vh, int tid) {
#pragma unroll
  for (int i = 0; i < 8; i++) {
    const int t = i >> 2;  // 0=Kh 1=Vh
    int r = (tid >> 3) + 32 * (i & 3);
    int c = tid & 7;
    const char* src = (t == 0 ? kh : vh) + r * 128 + c * 16;
    uint32_t dst = sdst + (uint32_t)t * TILE + (uint32_t)r * KSTRIDE + 16u * c;
    asm volatile("cp.async.cg.shared.global [%0], [%1], 16;" :: "r"(dst), "l"(src));
  }
}

__global__ void __launch_bounds__(256, 2)
attn_mma(float* __restrict__ O) {
  extern __shared__ __align__(16) char smem[];
  const uint32_t sb = smem_u32(smem);

  const int tid = threadIdx.x;
  const int w = tid >> 5, lane = tid & 31;
  const int g = lane >> 2, tq = lane & 3;

  const int qt = (int)gridDim.x - 1 - (int)blockIdx.x;  // heavy tiles first
  const int h = blockIdx.y, b = blockIdx.z;
  const int q0 = qt * BM;
  const int nkt = qt + 1;

  const size_t plane = ((size_t)b * Hn + h) * Ln * En;
  const char* kbh = reinterpret_cast<const char*>(Khg + plane);
  const char* vbh = reinterpret_cast<const char*>(Vhg + plane);

  // ---- Q fragments (scale*log2e folded) ----
  uint32_t qh[4][4];
  {
    const __half* r0p = Qhg + plane + (size_t)(q0 + 16 * w + g) * En;
    const __half* r1p = r0p + 8 * En;
#pragma unroll
    for (int k = 0; k < 4; k++) {
      qh[k][0] = *reinterpret_cast<const uint32_t*>(r0p + 16 * k + 2 * tq);
      qh[k][1] = *reinterpret_cast<const uint32_t*>(r1p + 16 * k + 2 * tq);
      qh[k][2] = *reinterpret_cast<const uint32_t*>(r0p + 16 * k + 2 * tq + 8);
      qh[k][3] = *reinterpret_cast<const uint32_t*>(r1p + 16 * k + 2 * tq + 8);
    }
  }

  float o[8][4];
#pragma unroll
  for (int j = 0; j < 8; j++) { o[j][0] = o[j][1] = o[j][2] = o[j][3] = 0.0f; }
  float lacc[4] = {0.0f, 0.0f, 0.0f, 0.0f};  // row sums via ones-MMA
  const int row0 = q0 + 16 * w + g, row1 = row0 + 8;

  // ldmatrix lane bases
  const uint32_t kmb = (uint32_t)(lane & 7) * KSTRIDE + (uint32_t)(lane >> 3) * 16;
  const uint32_t vmb = (uint32_t)(lane & 15) * KSTRIDE + (uint32_t)(lane >> 4) * 16;

  stage_cp(sb, kbh, vbh, tid);
  asm volatile("cp.async.commit_group;" ::: "memory");

  for (int kt = 0; kt < nkt; kt++) {
    const uint32_t cbuf = sb + (uint32_t)(kt & 1) * BUFB;
    const bool pf = (kt + 1 < nkt);
    if (pf) {
      size_t rb = (size_t)(kt + 1) * 128 * 128;
      stage_cp(sb + (uint32_t)((kt + 1) & 1) * BUFB, kbh + rb, vbh + rb, tid);
      asm volatile("cp.async.commit_group;" ::: "memory");
      asm volatile("cp.async.wait_group 1;" ::: "memory");
    } else {
      asm volatile("cp.async.wait_group 0;" ::: "memory");
    }
    __syncthreads();

    if (kt < nkt - 1) {
      // ================= non-diagonal tile: 2-stage software pipeline =================
      uint32_t kf0[8], kf1[8];   // double-buffered K fragments
      uint32_t vf[16];           // V fragments for current kp (loaded 1 stage early)
      uint32_t ph[4];            // P fragments (completed 1 stage late)
      float cb0[8], cb1[8];      // double-buffered raw S accumulators (cA|cB)

      // prologue: K fragments for jb=0
      ldsm_x4(kf0[0], kf0[1], kf0[2], kf0[3], cbuf + kmb);
      ldsm_x4(kf0[4], kf0[5], kf0[6], kf0[7], cbuf + kmb + 64);

#pragma unroll
      for (int jb = 0; jb < 16; jb++) {
        const int cur = jb & 1;
        uint32_t* kfc = cur ? kf1 : kf0;
        float* cc = cur ? cb1 : cb0;

        // (1) S-MMAs(jb): operands preloaded last stage; results consumed next stage
        cc[0] = cc[1] = cc[2] = cc[3] = 0.f;
        cc[4] = cc[5] = cc[6] = cc[7] = 0.f;
        mma16816(*reinterpret_cast<float(*)[4]>(cc), qh[0], kfc[0], kfc[1]);
        mma16816(*reinterpret_cast<float(*)[4]>(cc + 4), qh[1], kfc[2], kfc[3]);
        mma16816(*reinterpret_cast<float(*)[4]>(cc), qh[2], kfc[4], kfc[5]);
        mma16816(*reinterpret_cast<float(*)[4]>(cc + 4), qh[3], kfc[6], kfc[7]);

        // (2) prefetch K(jb+1)
        if (jb + 1 < 16) {
          uint32_t* kfn = cur ? kf0 : kf1;
          const uint32_t a = cbuf + kmb + (uint32_t)(jb + 1) * (8 * KSTRIDE);
          ldsm_x4(kfn[0], kfn[1], kfn[2], kfn[3], a);
          ldsm_x4(kfn[4], kfn[5], kfn[6], kfn[7], a + 64);
        }

        // (3) odd stages: prefetch V for kp=jb>>1 (consumed at stage jb+1)
        if (cur == 1) {
          const uint32_t vb = cbuf + TILE + vmb + (uint32_t)(jb >> 1) * (16 * KSTRIDE);
          ldsm_x4_t(vf[0], vf[1], vf[2], vf[3], vb);
          ldsm_x4_t(vf[4], vf[5], vf[6], vf[7], vb + 32);
          ldsm_x4_t(vf[8], vf[9], vf[10], vf[11], vb + 64);
          ldsm_x4_t(vf[12], vf[13], vf[14], vf[15], vb + 96);
        }

        // (4) softmax(jb-1): pack scores to fp16 pairs, ONE ex2.f16x2 per pair.
        //     Overlaps the tensor pipe working on S-MMAs(jb).
        if (jb >= 1) {
          const float* cp = (cur == 1) ? cb0 : cb1;
          const int pp = (jb - 1) & 1;
          ph[pp * 2 + 0] = ex2h2(packh(cp[0] + cp[4], cp[1] + cp[5]));
          ph[pp * 2 + 1] = ex2h2(packh(cp[2] + cp[6], cp[3] + cp[7]));
        }

        // (5) even stages >= 2: PV burst for kp=(jb-2)/2 (ph, vf both ready)
        if (cur == 0 && jb >= 2) {
          mma16816(lacc, ph, HONES, HONES);
#pragma unroll
          for (int j2 = 0; j2 < 4; j2++) {
            mma16816(o[2 * j2], ph, vf[4 * j2], vf[4 * j2 + 1]);
            mma16816(o[2 * j2 + 1], ph, vf[4 * j2 + 2], vf[4 * j2 + 3]);
          }
        }
      }
      // drain: softmax(15) then PV(kp=7)
      ph[2] = ex2h2(packh(cb1[0] + cb1[4], cb1[1] + cb1[5]));
      ph[3] = ex2h2(packh(cb1[2] + cb1[6], cb1[3] + cb1[7]));
      mma16816(lacc, ph, HONES, HONES);
#pragma unroll
      for (int j2 = 0; j2 < 4; j2++) {
        mma16816(o[2 * j2], ph, vf[4 * j2], vf[4 * j2 + 1]);
        mma16816(o[2 * j2 + 1], ph, vf[4 * j2 + 2], vf[4 * j2 + 3]);
      }
    } else {
      // ================= diagonal tile: simple masked kp loop =================
#pragma unroll
      for (int kp = 0; kp < 8; kp++) {
        if (kp > w) break;
        uint32_t ph[4];
#pragma unroll
        for (int jj = 0; jj < 2; jj++) {
          const int j = 2 * kp + jj;
          const uint32_t a = cbuf + kmb + (uint32_t)j * (8 * KSTRIDE);
          uint32_t b0, b1, b2, b3, b4, b5, b6, b7;
          ldsm_x4(b0, b1, b2, b3, a);
          ldsm_x4(b4, b5, b6, b7, a + 64);
          float cA[4] = {0.f, 0.f, 0.f, 0.f}, cB[4] = {0.f, 0.f, 0.f, 0.f};
          mma16816(cA, qh[0], b0, b1);
          mma16816(cB, qh[1], b2, b3);
          mma16816(cA, qh[2], b4, b5);
          mma16816(cB, qh[3], b6, b7);

          float f0 = cA[0] + cB[0], f1 = cA[1] + cB[1];
          float f2 = cA[2] + cB[2], f3 = cA[3] + cB[3];
          int kb = kt * 128 + 8 * j + 2 * tq;
          if (kb > row0) f0 = -1e30f;       // -> -inf in fp16 -> ex2 -> 0
          if (kb + 1 > row0) f1 = -1e30f;
          if (kb > row1) f2 = -1e30f;
          if (kb + 1 > row1) f3 = -1e30f;
          ph[jj * 2 + 0] = ex2h2(packh(f0, f1));
          ph[jj * 2 + 1] = ex2h2(packh(f2, f3));
        }
        mma16816(lacc, ph, HONES, HONES);
#pragma unroll
        for (int j2 = 0; j2 < 4; j2++) {
          uint32_t a = cbuf + TILE + vmb + (uint32_t)kp * (16 * KSTRIDE) + 32u * j2;
          uint32_t v0, v1, v2, v3;
          ldsm_x4_t(v0, v1, v2, v3, a);
          mma16816(o[2 * j2], ph, v0, v1);
          mma16816(o[2 * j2 + 1], ph, v2, v3);
        }
      }
    }
    __syncthreads();  // all warps done with cbuf before restage
  }

  // ---- epilogue: lacc holds exact row sums (no cross-lane reduce needed) ----
  const float i0 = 1.0f / lacc[0], i1 = 1.0f / lacc[2];
  float* r0p = O + ((size_t)(b * Ln + row0) * Hn + h) * En;
  float* r1p = r0p + 8 * (size_t)RS;
#pragma unroll
  for (int j = 0; j < 8; j++) {
    *reinterpret_cast<float2*>(r0p + 8 * j + 2 * tq) = make_float2(o[j][0] * i0, o[j][1] * i0);
    *reinterpret_cast<float2*>(r1p + 8 * j + 2 * tq) = make_float2(o[j][2] * i1, o[j][3] * i1);
  }
}

}  // namespace

extern "C" void kernel_launch(void* const* d_in, const int* in_sizes, int n_in,
                              void* d_out, int out_size) {
  (void)in_sizes; (void)n_in; (void)out_size;
  const float* Q = (const float*)d_in[0];
  const float* K = (const float*)d_in[1];
  const float* V = (const float*)d_in[2];
  float* O = (float*)d_out;

  prep<<<(Bn * Ln * Hn * (En / 4)) / 256, 256>>>(Q, K, V);

  cudaFuncSetAttribute(attn_mma, cudaFuncAttributeMaxDynamicSharedMemorySize, SMEM_TOTAL);
  dim3 grid(Ln / BM, Hn, Bn);  // (16 q-tiles, 16 heads, 2 batches)
  attn_mma<<<grid, 256, SMEM_TOTAL>>>(O);
}